// round 14
// baseline (speedup 1.0000x reference)
#include <cuda_runtime.h>
#include <stdint.h>

// LayoutBBox: in (B,12,64) f32 -> out (B,8,128,128) f32
// out[b,c,h,w] = max_n xy[n,h,w]*cls[n,c], xy = max(lx(w)*gx(h), ly(h)*gy(w))
// prep: exact per-(b,w) column masks, pair-union row masks, packed records.
// main: one row-pair per CTA; each pixel's 64-box mask SPLIT across two
//       threads (ty=0: boxes 0-31, ty=1: boxes 32-63) -> warp-max trip count
//       halves and warp count doubles. Partners merge via smem at the end.

constexpr int Wd   = 128;
constexpr int Hd   = 128;
constexpr int NP   = Hd / 2;       // 64 row pairs
constexpr int NUMB = 64;
constexpr int NCLS = 8;
constexpr int INCH = 12;
constexpr int MAXB = 16;

using u64 = unsigned long long;

__device__ __forceinline__ u64 pk(float lo, float hi) {
    u64 r; asm("mov.b64 %0,{%1,%2};" : "=l"(r) : "f"(lo), "f"(hi)); return r;
}
__device__ __forceinline__ void upk(float& lo, float& hi, u64 v) {
    asm("mov.b64 {%0,%1},%2;" : "=f"(lo), "=f"(hi) : "l"(v));
}
__device__ __forceinline__ u64 pmul(u64 a, u64 b) {
    u64 r; asm("mul.rn.f32x2 %0,%1,%2;" : "=l"(r) : "l"(a), "l"(b)); return r;
}

__device__ ulonglong2 g_cmask[MAXB][Wd];    // (Mlx, Mgw) per (b,w)
__device__ ulonglong2 g_rmask2[MAXB][NP];   // pair-union (Mgh, Mly)
__device__ float4     g_p [MAXB][NUMB];     // x1, x2, y1, y2
__device__ ulonglong2 g_ca[MAXB][NUMB];     // packed (c0,c1),(c2,c3)
__device__ ulonglong2 g_cb[MAXB][NUMB];     // packed (c4,c5),(c6,c7)

// ---------------- prep kernel: grid (2, B), block 1024 ----------------
__global__ void prep_kernel(const float* __restrict__ in)
{
    const int b   = blockIdx.y;
    const int tid = threadIdx.x;
    const float* base = in + (size_t)b * INCH * NUMB;

    if (blockIdx.x == 0) {
        if (tid < NUMB) {
            float xc = base[0 * NUMB + tid] * 128.0f;
            float yc = base[1 * NUMB + tid] * 128.0f;
            float bw = base[2 * NUMB + tid] * 128.0f;
            float bh = base[3 * NUMB + tid] * 128.0f;
            g_p[b][tid] = make_float4(xc - 0.5f * bw, xc + 0.5f * bw,
                                      yc - 0.5f * bh, yc + 0.5f * bh);
            ulonglong2 ca, cb;
            ca.x = pk(base[4 * NUMB + tid],  base[5 * NUMB + tid]);
            ca.y = pk(base[6 * NUMB + tid],  base[7 * NUMB + tid]);
            cb.x = pk(base[8 * NUMB + tid],  base[9 * NUMB + tid]);
            cb.y = pk(base[10 * NUMB + tid], base[11 * NUMB + tid]);
            g_ca[b][tid] = ca;
            g_cb[b][tid] = cb;
        }
        {   // column masks, byte-parallel (1024 slots)
            int w = tid >> 3, j = tid & 7;
            float wf = (float)w;
            unsigned blx = 0, bgw = 0;
            #pragma unroll
            for (int k = 0; k < 8; k++) {
                int n = 8 * j + k;
                float xc = base[0 * NUMB + n] * 128.0f;
                float bw = base[2 * NUMB + n] * 128.0f;
                float x1 = xc - 0.5f * bw, x2 = xc + 0.5f * bw;
                if (fabsf(wf - x1) < 1.0f || fabsf(x2 - wf) < 1.0f) blx |= 1u << k;
                if (wf > x1 && wf < x2)                             bgw |= 1u << k;
            }
            unsigned char* dst = (unsigned char*)&g_cmask[b][w];
            dst[j]     = (unsigned char)blx;
            dst[8 + j] = (unsigned char)bgw;
        }
    } else {
        // pair-union row masks (512 slots)
        if (tid < NP * 8) {
            int p = tid >> 3, j = tid & 7;
            float hf0 = (float)(2 * p);
            float hf1 = hf0 + 1.0f;
            unsigned bgh = 0, bly = 0;
            #pragma unroll
            for (int k = 0; k < 8; k++) {
                int n = 8 * j + k;
                float yc = base[1 * NUMB + n] * 128.0f;
                float bh = base[3 * NUMB + n] * 128.0f;
                float y1 = yc - 0.5f * bh, y2 = yc + 0.5f * bh;
                bool g0 = (hf0 > y1 && hf0 < y2);
                bool g1 = (hf1 > y1 && hf1 < y2);
                if (g0 || g1) bgh |= 1u << k;
                bool l0 = (fabsf(hf0 - y1) < 1.0f || fabsf(y2 - hf0) < 1.0f);
                bool l1 = (fabsf(hf1 - y1) < 1.0f || fabsf(y2 - hf1) < 1.0f);
                if (l0 || l1) bly |= 1u << k;
            }
            unsigned char* dst = (unsigned char*)&g_rmask2[b][p];
            dst[j]     = (unsigned char)bgh;
            dst[8 + j] = (unsigned char)bly;
        }
    }
    asm volatile("griddepcontrol.launch_dependents;" ::: "memory");
}

// ---- main kernel: grid (NP, B), block (128, 2); pair per CTA, split mask ----
__global__ __launch_bounds__(256)
void layout_bbox_main(float* __restrict__ out)
{
    __shared__ float2     sspx[NUMB];         // (x1, x2)
    __shared__ ulonglong2 sht [NUMB];         // (gx0,ly0),(gx1,ly1) for this pair
    __shared__ ulonglong2 sca [NUMB];
    __shared__ ulonglong2 scb [NUMB];
    __shared__ float      sx[16][132];        // partner exchange, conflict-free

    const int tx  = threadIdx.x;              // w
    const int ty  = threadIdx.y;              // mask half
    const int tid = ty * Wd + tx;
    const int b   = blockIdx.y;
    const int p   = blockIdx.x;
    const int h0  = 2 * p;
    const float wf = (float)tx;

    asm volatile("griddepcontrol.wait;" ::: "memory");

    // ---- prologue staging: 256 threads, 4 groups of 64 ----
    if (tid < NUMB) {
        float4 q = g_p[b][tid];
        sspx[tid] = make_float2(q.x, q.y);
    } else if (tid < 2 * NUMB) {
        sca[tid - NUMB] = g_ca[b][tid - NUMB];
    } else if (tid < 3 * NUMB) {
        scb[tid - 2 * NUMB] = g_cb[b][tid - 2 * NUMB];
    } else {
        int n = tid - 3 * NUMB;
        float4 q = g_p[b][n];                 // need .z, .w
        float hf0 = (float)h0, hf1 = hf0 + 1.0f;
        float dy1 = hf0 - q.z, dy2 = q.w - hf0;
        float gx0 = __saturatef(dy1) * __saturatef(dy2);
        float ly0 = fmaxf(0.0f, fmaxf(1.0f - fabsf(dy1), 1.0f - fabsf(dy2)));
        dy1 = hf1 - q.z; dy2 = q.w - hf1;
        float gx1 = __saturatef(dy1) * __saturatef(dy2);
        float ly1 = fmaxf(0.0f, fmaxf(1.0f - fabsf(dy1), 1.0f - fabsf(dy2)));
        ulonglong2 e;
        e.x = pk(gx0, ly0);
        e.y = pk(gx1, ly1);
        sht[n] = e;
    }

    const ulonglong2 cm  = g_cmask[b][tx];
    const ulonglong2 rmu = g_rmask2[b][p];
    const u64 m64 = (cm.x & rmu.x) | (cm.y & rmu.y);   // exact pair-union set
    unsigned m = (ty == 0) ? (unsigned)m64 : (unsigned)(m64 >> 32);
    const int nbase = ty << 5;

    __syncthreads();

    float a0 = 0.f, a1 = 0.f, a2 = 0.f, a3 = 0.f;     // row h0
    float a4 = 0.f, a5 = 0.f, a6 = 0.f, a7 = 0.f;
    float b0 = 0.f, b1 = 0.f, b2 = 0.f, b3 = 0.f;     // row h0+1
    float b4 = 0.f, b5 = 0.f, b6 = 0.f, b7 = 0.f;

    while (m) {                                       // divergent, half mask
        int n = nbase + (__ffs(m) - 1);
        m &= m - 1;

        float2 xb = sspx[n];                          // LDS.64
        float dx1 = wf - xb.x, dx2 = xb.y - wf;
        float lx = fmaxf(0.0f, fmaxf(1.0f - fabsf(dx1), 1.0f - fabsf(dx2)));
        float gy = __saturatef(dx1) * __saturatef(dx2);
        u64 wv = pk(lx, gy);

        ulonglong2 hv = sht[n];                       // LDS.128
        float t0, t1;
        upk(t0, t1, pmul(wv, hv.x));
        float xy0 = fmaxf(t0, t1);
        upk(t0, t1, pmul(wv, hv.y));
        float xy1 = fmaxf(t0, t1);

        u64 x0 = pk(xy0, xy0);
        u64 x1 = pk(xy1, xy1);
        ulonglong2 ca = sca[n];                       // LDS.128
        ulonglong2 cb = scb[n];                       // LDS.128
        float p0, p1;
        upk(p0, p1, pmul(x0, ca.x)); a0 = fmaxf(a0, p0); a1 = fmaxf(a1, p1);
        upk(p0, p1, pmul(x0, ca.y)); a2 = fmaxf(a2, p0); a3 = fmaxf(a3, p1);
        upk(p0, p1, pmul(x0, cb.x)); a4 = fmaxf(a4, p0); a5 = fmaxf(a5, p1);
        upk(p0, p1, pmul(x0, cb.y)); a6 = fmaxf(a6, p0); a7 = fmaxf(a7, p1);
        upk(p0, p1, pmul(x1, ca.x)); b0 = fmaxf(b0, p0); b1 = fmaxf(b1, p1);
        upk(p0, p1, pmul(x1, ca.y)); b2 = fmaxf(b2, p0); b3 = fmaxf(b3, p1);
        upk(p0, p1, pmul(x1, cb.x)); b4 = fmaxf(b4, p0); b5 = fmaxf(b5, p1);
        upk(p0, p1, pmul(x1, cb.y)); b6 = fmaxf(b6, p0); b7 = fmaxf(b7, p1);
    }

    // ---- partner merge: ty0 gives row1 accs, ty1 gives row0 accs ----
    if (ty == 0) {
        sx[8][tx] = b0;  sx[9][tx] = b1;  sx[10][tx] = b2; sx[11][tx] = b3;
        sx[12][tx] = b4; sx[13][tx] = b5; sx[14][tx] = b6; sx[15][tx] = b7;
    } else {
        sx[0][tx] = a0;  sx[1][tx] = a1;  sx[2][tx] = a2;  sx[3][tx] = a3;
        sx[4][tx] = a4;  sx[5][tx] = a5;  sx[6][tx] = a6;  sx[7][tx] = a7;
    }
    __syncthreads();

    const int cs = Hd * Wd;
    if (ty == 0) {      // merge + store row h0
        float* o = out + (((size_t)b * NCLS) * Hd + h0) * Wd + tx;
        o[0 * cs] = fmaxf(a0, sx[0][tx]); o[1 * cs] = fmaxf(a1, sx[1][tx]);
        o[2 * cs] = fmaxf(a2, sx[2][tx]); o[3 * cs] = fmaxf(a3, sx[3][tx]);
        o[4 * cs] = fmaxf(a4, sx[4][tx]); o[5 * cs] = fmaxf(a5, sx[5][tx]);
        o[6 * cs] = fmaxf(a6, sx[6][tx]); o[7 * cs] = fmaxf(a7, sx[7][tx]);
    } else {            // merge + store row h0+1
        float* o = out + (((size_t)b * NCLS) * Hd + h0 + 1) * Wd + tx;
        o[0 * cs] = fmaxf(b0, sx[8][tx]);  o[1 * cs] = fmaxf(b1, sx[9][tx]);
        o[2 * cs] = fmaxf(b2, sx[10][tx]); o[3 * cs] = fmaxf(b3, sx[11][tx]);
        o[4 * cs] = fmaxf(b4, sx[12][tx]); o[5 * cs] = fmaxf(b5, sx[13][tx]);
        o[6 * cs] = fmaxf(b6, sx[14][tx]); o[7 * cs] = fmaxf(b7, sx[15][tx]);
    }
}

extern "C" void kernel_launch(void* const* d_in, const int* in_sizes, int n_in,
                              void* d_out, int out_size)
{
    const float* in = (const float*)d_in[0];
    float* out = (float*)d_out;
    int B = in_sizes[0] / (INCH * NUMB);   // 16

    prep_kernel<<<dim3(2, B), 1024>>>(in);

    cudaLaunchConfig_t cfg = {};
    cfg.gridDim  = dim3(NP, B);            // (64, B) = 1024 CTAs
    cfg.blockDim = dim3(Wd, 2);            // 128 x 2 = 256 threads
    cudaLaunchAttribute attr[1];
    attr[0].id = cudaLaunchAttributeProgrammaticStreamSerialization;
    attr[0].val.programmaticStreamSerializationAllowed = 1;
    cfg.attrs = attr;
    cfg.numAttrs = 1;
    cudaLaunchKernelEx(&cfg, layout_bbox_main, out);
}

// round 15
// speedup vs baseline: 1.0030x; 1.0030x over previous
#include <cuda_runtime.h>
#include <stdint.h>

// LayoutBBox: in (B,12,64) f32 -> out (B,8,128,128) f32
// out[b,c,h,w] = max_n xy[n,h,w]*cls[n,c], xy = max(lx(w)*gx(h), ly(h)*gy(w))
// SINGLE fused kernel. Per-CTA prep (records + exact byte-parallel bitmasks +
// row-profile table for the CTA's two interleaved row pairs), then the R13
// pair-union divergent visit loop. No second launch, no PDL gap.

constexpr int Wd   = 128;
constexpr int Hd   = 128;
constexpr int NP   = Hd / 2;       // 64 row pairs
constexpr int NUMB = 64;
constexpr int NCLS = 8;
constexpr int INCH = 12;

using u64 = unsigned long long;

__device__ __forceinline__ u64 pk(float lo, float hi) {
    u64 r; asm("mov.b64 %0,{%1,%2};" : "=l"(r) : "f"(lo), "f"(hi)); return r;
}
__device__ __forceinline__ void upk(float& lo, float& hi, u64 v) {
    asm("mov.b64 {%0,%1},%2;" : "=f"(lo), "=f"(hi) : "l"(v));
}
__device__ __forceinline__ u64 pmul(u64 a, u64 b) {
    u64 r; asm("mul.rn.f32x2 %0,%1,%2;" : "=l"(r) : "l"(a), "l"(b)); return r;
}

// ---- fused kernel: grid (NP/2, B), block (128, 2); one row-pair/thread ----
__global__ __launch_bounds__(256)
void layout_bbox_fused(const float* __restrict__ in, float* __restrict__ out)
{
    __shared__ float2     sspx[NUMB];         // (x1, x2)
    __shared__ float2     sspy[NUMB];         // (y1, y2)
    __shared__ ulonglong2 sca [NUMB];         // packed (c0,c1),(c2,c3)
    __shared__ ulonglong2 scb [NUMB];         // packed (c4,c5),(c6,c7)
    __shared__ ulonglong2 sht [2 * NUMB];     // [local pair][n]: (gx0,ly0),(gx1,ly1)
    __shared__ ulonglong2 scm [Wd];           // (Mlx, Mgw) per w
    __shared__ ulonglong2 srm [2];            // pair-union (Mgh, Mly) per local pair

    const int tx  = threadIdx.x;              // w
    const int ty  = threadIdx.y;
    const int tid = ty * Wd + tx;
    const int b   = blockIdx.y;
    const int p   = blockIdx.x + ty * (NP / 2);   // interleaved pair index
    const int h0  = 2 * p;
    const float wf = (float)tx;

    // ---- stage 1: box records from input (threads 0..63) ----
    if (tid < NUMB) {
        const float* base = in + (size_t)b * INCH * NUMB + tid;
        float xc = base[0 * NUMB] * 128.0f;
        float yc = base[1 * NUMB] * 128.0f;
        float bw = base[2 * NUMB] * 128.0f;
        float bh = base[3 * NUMB] * 128.0f;
        sspx[tid] = make_float2(xc - 0.5f * bw, xc + 0.5f * bw);
        sspy[tid] = make_float2(yc - 0.5f * bh, yc + 0.5f * bh);
        ulonglong2 ca, cb;
        ca.x = pk(base[4 * NUMB],  base[5 * NUMB]);
        ca.y = pk(base[6 * NUMB],  base[7 * NUMB]);
        cb.x = pk(base[8 * NUMB],  base[9 * NUMB]);
        cb.y = pk(base[10 * NUMB], base[11 * NUMB]);
        sca[tid] = ca;
        scb[tid] = cb;
    }
    __syncthreads();

    // ---- stage 2: masks + row-profile table ----
    // column masks: 1024 byte-slots, 4 per thread (reads sspx: LDS.64)
    #pragma unroll
    for (int s = tid; s < Wd * 8; s += Wd * 2) {
        int w = s >> 3, j = s & 7;
        float wfs = (float)w;
        unsigned blx = 0, bgw = 0;
        #pragma unroll
        for (int k = 0; k < 8; k++) {
            float2 x = sspx[8 * j + k];
            if (fabsf(wfs - x.x) < 1.0f || fabsf(x.y - wfs) < 1.0f) blx |= 1u << k;
            if (wfs > x.x && wfs < x.y)                             bgw |= 1u << k;
        }
        unsigned char* dst = (unsigned char*)&scm[w];
        dst[j]     = (unsigned char)blx;
        dst[8 + j] = (unsigned char)bgw;
    }
    // pair-union row masks: 16 byte-slots (threads 0..15)
    if (tid < 16) {
        int local = tid >> 3, j = tid & 7;
        int pw = blockIdx.x + local * (NP / 2);
        float hf0 = (float)(2 * pw);
        float hf1 = hf0 + 1.0f;
        unsigned bgh = 0, bly = 0;
        #pragma unroll
        for (int k = 0; k < 8; k++) {
            float2 y = sspy[8 * j + k];
            bool g0 = (hf0 > y.x && hf0 < y.y);
            bool g1 = (hf1 > y.x && hf1 < y.y);
            if (g0 || g1) bgh |= 1u << k;
            bool l0 = (fabsf(hf0 - y.x) < 1.0f || fabsf(y.y - hf0) < 1.0f);
            bool l1 = (fabsf(hf1 - y.x) < 1.0f || fabsf(y.y - hf1) < 1.0f);
            if (l0 || l1) bly |= 1u << k;
        }
        unsigned char* dst = (unsigned char*)&srm[local];
        dst[j]     = (unsigned char)bgh;
        dst[8 + j] = (unsigned char)bly;
    }
    // row-profile table for both pairs: 128 entries (threads 128..255)
    if (tid >= 128) {
        int wkr   = tid - 128;
        int local = wkr >> 6;
        int n     = wkr & 63;
        int pw    = blockIdx.x + local * (NP / 2);
        float hf0 = (float)(2 * pw);
        float hf1 = hf0 + 1.0f;
        float2 y  = sspy[n];
        float dy1 = hf0 - y.x, dy2 = y.y - hf0;
        float gx0 = __saturatef(dy1) * __saturatef(dy2);
        float ly0 = fmaxf(0.0f, fmaxf(1.0f - fabsf(dy1), 1.0f - fabsf(dy2)));
        dy1 = hf1 - y.x; dy2 = y.y - hf1;
        float gx1 = __saturatef(dy1) * __saturatef(dy2);
        float ly1 = fmaxf(0.0f, fmaxf(1.0f - fabsf(dy1), 1.0f - fabsf(dy2)));
        ulonglong2 e;
        e.x = pk(gx0, ly0);
        e.y = pk(gx1, ly1);
        sht[local * NUMB + n] = e;
    }
    __syncthreads();

    // ---- stage 3: pair-union divergent visit loop (R13 structure) ----
    const ulonglong2 cm  = scm[tx];
    const ulonglong2 rmu = srm[ty];
    u64 m = (cm.x & rmu.x) | (cm.y & rmu.y);          // exact pair-union set

    const ulonglong2* __restrict__ ht = sht + ty * NUMB;

    float a0 = 0.f, a1 = 0.f, a2 = 0.f, a3 = 0.f;
    float a4 = 0.f, a5 = 0.f, a6 = 0.f, a7 = 0.f;
    float b0 = 0.f, b1 = 0.f, b2 = 0.f, b3 = 0.f;
    float b4 = 0.f, b5 = 0.f, b6 = 0.f, b7 = 0.f;

    while (m) {                                       // divergent per-lane loop
        int n = __ffsll((long long)m) - 1;
        m &= m - 1;

        float2 xb = sspx[n];                          // LDS.64
        float dx1 = wf - xb.x, dx2 = xb.y - wf;
        float lx = fmaxf(0.0f, fmaxf(1.0f - fabsf(dx1), 1.0f - fabsf(dx2)));
        float gy = __saturatef(dx1) * __saturatef(dx2);
        u64 wv = pk(lx, gy);

        ulonglong2 hv = ht[n];                        // LDS.128: (gx,ly) both rows
        float t0, t1;
        upk(t0, t1, pmul(wv, hv.x));                  // (lx*gx0, gy*ly0)
        float xy0 = fmaxf(t0, t1);
        upk(t0, t1, pmul(wv, hv.y));
        float xy1 = fmaxf(t0, t1);

        u64 x0 = pk(xy0, xy0);
        u64 x1 = pk(xy1, xy1);
        ulonglong2 ca = sca[n];                       // LDS.128
        ulonglong2 cb = scb[n];                       // LDS.128
        float p0, p1;
        upk(p0, p1, pmul(x0, ca.x)); a0 = fmaxf(a0, p0); a1 = fmaxf(a1, p1);
        upk(p0, p1, pmul(x0, ca.y)); a2 = fmaxf(a2, p0); a3 = fmaxf(a3, p1);
        upk(p0, p1, pmul(x0, cb.x)); a4 = fmaxf(a4, p0); a5 = fmaxf(a5, p1);
        upk(p0, p1, pmul(x0, cb.y)); a6 = fmaxf(a6, p0); a7 = fmaxf(a7, p1);
        upk(p0, p1, pmul(x1, ca.x)); b0 = fmaxf(b0, p0); b1 = fmaxf(b1, p1);
        upk(p0, p1, pmul(x1, ca.y)); b2 = fmaxf(b2, p0); b3 = fmaxf(b3, p1);
        upk(p0, p1, pmul(x1, cb.x)); b4 = fmaxf(b4, p0); b5 = fmaxf(b5, p1);
        upk(p0, p1, pmul(x1, cb.y)); b6 = fmaxf(b6, p0); b7 = fmaxf(b7, p1);
    }

    float* o = out + (((size_t)b * NCLS) * Hd + h0) * Wd + tx;
    const int cs = Hd * Wd;
    o[0 * cs] = a0; o[1 * cs] = a1; o[2 * cs] = a2; o[3 * cs] = a3;
    o[4 * cs] = a4; o[5 * cs] = a5; o[6 * cs] = a6; o[7 * cs] = a7;
    o += Wd;
    o[0 * cs] = b0; o[1 * cs] = b1; o[2 * cs] = b2; o[3 * cs] = b3;
    o[4 * cs] = b4; o[5 * cs] = b5; o[6 * cs] = b6; o[7 * cs] = b7;
}

extern "C" void kernel_launch(void* const* d_in, const int* in_sizes, int n_in,
                              void* d_out, int out_size)
{
    const float* in = (const float*)d_in[0];
    float* out = (float*)d_out;
    int B = in_sizes[0] / (INCH * NUMB);   // 16

    dim3 grid(NP / 2, B);                  // (32, B) = 512 CTAs
    dim3 block(Wd, 2);                     // 128 x 2 = 256 threads
    layout_bbox_fused<<<grid, block>>>(in, out);
}

// round 17
// speedup vs baseline: 1.0375x; 1.0344x over previous
#include <cuda_runtime.h>
#include <stdint.h>

// LayoutBBox: in (B,12,64) f32 -> out (B,8,128,128) f32
// out[b,c,h,w] = max_n xy[n,h,w]*cls[n,c], xy = max(lx(w)*gx(h), ly(h)*gy(w))
// prep: exact per-(b,w) column masks, pair-union row masks, packed records.
// main: 2 rows/thread (row pair), UNIFORM counted visit loop (warp-max trips,
//       dummy visits contribute exactly 0), unrolled x2 for LDS latency overlap.

constexpr int Wd   = 128;
constexpr int Hd   = 128;
constexpr int NP   = Hd / 2;       // 64 row pairs
constexpr int NUMB = 64;
constexpr int NCLS = 8;
constexpr int INCH = 12;
constexpr int MAXB = 16;

using u64 = unsigned long long;

__device__ __forceinline__ u64 pk(float lo, float hi) {
    u64 r; asm("mov.b64 %0,{%1,%2};" : "=l"(r) : "f"(lo), "f"(hi)); return r;
}
__device__ __forceinline__ void upk(float& lo, float& hi, u64 v) {
    asm("mov.b64 {%0,%1},%2;" : "=f"(lo), "=f"(hi) : "l"(v));
}
__device__ __forceinline__ u64 pmul(u64 a, u64 b) {
    u64 r; asm("mul.rn.f32x2 %0,%1,%2;" : "=l"(r) : "l"(a), "l"(b)); return r;
}

__device__ ulonglong2 g_cmask[MAXB][Wd];    // (Mlx, Mgw) per (b,w)
__device__ ulonglong2 g_rmask2[MAXB][NP];   // pair-union (Mgh, Mly)
__device__ float4     g_p [MAXB][NUMB];     // x1, x2, y1, y2
__device__ ulonglong2 g_ca[MAXB][NUMB];     // packed (c0,c1),(c2,c3)
__device__ ulonglong2 g_cb[MAXB][NUMB];     // packed (c4,c5),(c6,c7)

// ---------------- prep kernel: grid (2, B), block 1024 ----------------
__global__ void prep_kernel(const float* __restrict__ in)
{
    const int b   = blockIdx.y;
    const int tid = threadIdx.x;
    const float* base = in + (size_t)b * INCH * NUMB;

    if (blockIdx.x == 0) {
        if (tid < NUMB) {
            float xc = base[0 * NUMB + tid] * 128.0f;
            float yc = base[1 * NUMB + tid] * 128.0f;
            float bw = base[2 * NUMB + tid] * 128.0f;
            float bh = base[3 * NUMB + tid] * 128.0f;
            g_p[b][tid] = make_float4(xc - 0.5f * bw, xc + 0.5f * bw,
                                      yc - 0.5f * bh, yc + 0.5f * bh);
            ulonglong2 ca, cb;
            ca.x = pk(base[4 * NUMB + tid],  base[5 * NUMB + tid]);
            ca.y = pk(base[6 * NUMB + tid],  base[7 * NUMB + tid]);
            cb.x = pk(base[8 * NUMB + tid],  base[9 * NUMB + tid]);
            cb.y = pk(base[10 * NUMB + tid], base[11 * NUMB + tid]);
            g_ca[b][tid] = ca;
            g_cb[b][tid] = cb;
        }
        {   // column masks, byte-parallel (1024 slots)
            int w = tid >> 3, j = tid & 7;
            float wf = (float)w;
            unsigned blx = 0, bgw = 0;
            #pragma unroll
            for (int k = 0; k < 8; k++) {
                int n = 8 * j + k;
                float xc = base[0 * NUMB + n] * 128.0f;
                float bw = base[2 * NUMB + n] * 128.0f;
                float x1 = xc - 0.5f * bw, x2 = xc + 0.5f * bw;
                if (fabsf(wf - x1) < 1.0f || fabsf(x2 - wf) < 1.0f) blx |= 1u << k;
                if (wf > x1 && wf < x2)                             bgw |= 1u << k;
            }
            unsigned char* dst = (unsigned char*)&g_cmask[b][w];
            dst[j]     = (unsigned char)blx;
            dst[8 + j] = (unsigned char)bgw;
        }
    } else {
        // pair-union row masks (512 slots)
        if (tid < NP * 8) {
            int p = tid >> 3, j = tid & 7;
            float hf0 = (float)(2 * p);
            float hf1 = hf0 + 1.0f;
            unsigned bgh = 0, bly = 0;
            #pragma unroll
            for (int k = 0; k < 8; k++) {
                int n = 8 * j + k;
                float yc = base[1 * NUMB + n] * 128.0f;
                float bh = base[3 * NUMB + n] * 128.0f;
                float y1 = yc - 0.5f * bh, y2 = yc + 0.5f * bh;
                bool g0 = (hf0 > y1 && hf0 < y2);
                bool g1 = (hf1 > y1 && hf1 < y2);
                if (g0 || g1) bgh |= 1u << k;
                bool l0 = (fabsf(hf0 - y1) < 1.0f || fabsf(y2 - hf0) < 1.0f);
                bool l1 = (fabsf(hf1 - y1) < 1.0f || fabsf(y2 - hf1) < 1.0f);
                if (l0 || l1) bly |= 1u << k;
            }
            unsigned char* dst = (unsigned char*)&g_rmask2[b][p];
            dst[j]     = (unsigned char)bgh;
            dst[8 + j] = (unsigned char)bly;
        }
    }
    asm volatile("griddepcontrol.launch_dependents;" ::: "memory");
}

// -------- main kernel: grid (NP/2, B), block (128, 2); one row-pair/thread ----
__global__ __launch_bounds__(256)
void layout_bbox_main(float* __restrict__ out)
{
    __shared__ float2     sspx[NUMB];         // (x1, x2)
    __shared__ ulonglong2 sht2[2 * NUMB];     // [local pair][n]: (gx0,ly0),(gx1,ly1)
    __shared__ ulonglong2 sca [NUMB];
    __shared__ ulonglong2 scb [NUMB];

    const int tx  = threadIdx.x;                      // w
    const int ty  = threadIdx.y;
    const int tid = ty * Wd + tx;
    const int b   = blockIdx.y;
    const int p   = blockIdx.x + ty * (NP / 2);       // interleaved pair index
    const int h0  = 2 * p;
    const float wf = (float)tx;

    asm volatile("griddepcontrol.wait;" ::: "memory");

    // ---- prologue staging ----
    if (tid < NUMB) {
        float4 q = g_p[b][tid];
        sspx[tid] = make_float2(q.x, q.y);
    } else if (tid < 2 * NUMB) {
        sca[tid - NUMB] = g_ca[b][tid - NUMB];
    } else if (tid < 3 * NUMB) {
        scb[tid - 2 * NUMB] = g_cb[b][tid - 2 * NUMB];
    }
    if (tid >= 128) {                                 // row-profile table
        int wkr   = tid - 128;
        int local = wkr >> 6;
        int n     = wkr & 63;
        int pw    = blockIdx.x + local * (NP / 2);
        float hf0 = (float)(2 * pw);
        float hf1 = hf0 + 1.0f;
        float4 q  = g_p[b][n];
        float dy1 = hf0 - q.z, dy2 = q.w - hf0;
        float gx0 = __saturatef(dy1) * __saturatef(dy2);
        float ly0 = fmaxf(0.0f, fmaxf(1.0f - fabsf(dy1), 1.0f - fabsf(dy2)));
        dy1 = hf1 - q.z; dy2 = q.w - hf1;
        float gx1 = __saturatef(dy1) * __saturatef(dy2);
        float ly1 = fmaxf(0.0f, fmaxf(1.0f - fabsf(dy1), 1.0f - fabsf(dy2)));
        ulonglong2 e;
        e.x = pk(gx0, ly0);
        e.y = pk(gx1, ly1);
        sht2[local * NUMB + n] = e;
    }

    const ulonglong2 cm  = g_cmask[b][tx];
    const ulonglong2 rmu = g_rmask2[b][p];
    u64 m = (cm.x & rmu.x) | (cm.y & rmu.y);          // exact pair-union set

    __syncthreads();

    const ulonglong2* __restrict__ ht = sht2 + ty * NUMB;

    float a0 = 0.f, a1 = 0.f, a2 = 0.f, a3 = 0.f;
    float a4 = 0.f, a5 = 0.f, a6 = 0.f, a7 = 0.f;
    float b0 = 0.f, b1 = 0.f, b2 = 0.f, b3 = 0.f;
    float b4 = 0.f, b5 = 0.f, b6 = 0.f, b7 = 0.f;

    // Uniform counted loop over warp-max trips; exhausted lanes visit box 0,
    // whose contribution is exactly 0 (mask == positivity of the profiles).
    int cnt  = __popcll(m);
    int maxc = __reduce_max_sync(0xFFFFFFFFu, cnt);

    for (int i = 0; i < maxc; i += 2) {
        int n0 = m ? (__ffsll((long long)m) - 1) : 0;  m &= m - 1;
        int n1 = m ? (__ffsll((long long)m) - 1) : 0;  m &= m - 1;

        // issue all loads for both trips first (LDS latency overlap)
        float2     xb0 = sspx[n0];
        ulonglong2 hv0 = ht[n0];
        ulonglong2 ca0 = sca[n0];
        ulonglong2 cb0 = scb[n0];
        float2     xb1 = sspx[n1];
        ulonglong2 hv1 = ht[n1];
        ulonglong2 ca1 = sca[n1];
        ulonglong2 cb1 = scb[n1];

        // ---- trip 0 ----
        float dx1 = wf - xb0.x, dx2 = xb0.y - wf;
        float lx = fmaxf(0.0f, fmaxf(1.0f - fabsf(dx1), 1.0f - fabsf(dx2)));
        float gy = __saturatef(dx1) * __saturatef(dx2);
        u64 wv = pk(lx, gy);
        float t0, t1;
        upk(t0, t1, pmul(wv, hv0.x));
        float xy0 = fmaxf(t0, t1);
        upk(t0, t1, pmul(wv, hv0.y));
        float xy1 = fmaxf(t0, t1);
        u64 x0 = pk(xy0, xy0);
        u64 x1 = pk(xy1, xy1);
        float p0, p1;
        upk(p0, p1, pmul(x0, ca0.x)); a0 = fmaxf(a0, p0); a1 = fmaxf(a1, p1);
        upk(p0, p1, pmul(x0, ca0.y)); a2 = fmaxf(a2, p0); a3 = fmaxf(a3, p1);
        upk(p0, p1, pmul(x0, cb0.x)); a4 = fmaxf(a4, p0); a5 = fmaxf(a5, p1);
        upk(p0, p1, pmul(x0, cb0.y)); a6 = fmaxf(a6, p0); a7 = fmaxf(a7, p1);
        upk(p0, p1, pmul(x1, ca0.x)); b0 = fmaxf(b0, p0); b1 = fmaxf(b1, p1);
        upk(p0, p1, pmul(x1, ca0.y)); b2 = fmaxf(b2, p0); b3 = fmaxf(b3, p1);
        upk(p0, p1, pmul(x1, cb0.x)); b4 = fmaxf(b4, p0); b5 = fmaxf(b5, p1);
        upk(p0, p1, pmul(x1, cb0.y)); b6 = fmaxf(b6, p0); b7 = fmaxf(b7, p1);

        // ---- trip 1 ----
        dx1 = wf - xb1.x; dx2 = xb1.y - wf;
        lx = fmaxf(0.0f, fmaxf(1.0f - fabsf(dx1), 1.0f - fabsf(dx2)));
        gy = __saturatef(dx1) * __saturatef(dx2);
        wv = pk(lx, gy);
        upk(t0, t1, pmul(wv, hv1.x));
        xy0 = fmaxf(t0, t1);
        upk(t0, t1, pmul(wv, hv1.y));
        xy1 = fmaxf(t0, t1);
        x0 = pk(xy0, xy0);
        x1 = pk(xy1, xy1);
        upk(p0, p1, pmul(x0, ca1.x)); a0 = fmaxf(a0, p0); a1 = fmaxf(a1, p1);
        upk(p0, p1, pmul(x0, ca1.y)); a2 = fmaxf(a2, p0); a3 = fmaxf(a3, p1);
        upk(p0, p1, pmul(x0, cb1.x)); a4 = fmaxf(a4, p0); a5 = fmaxf(a5, p1);
        upk(p0, p1, pmul(x0, cb1.y)); a6 = fmaxf(a6, p0); a7 = fmaxf(a7, p1);
        upk(p0, p1, pmul(x1, ca1.x)); b0 = fmaxf(b0, p0); b1 = fmaxf(b1, p1);
        upk(p0, p1, pmul(x1, ca1.y)); b2 = fmaxf(b2, p0); b3 = fmaxf(b3, p1);
        upk(p0, p1, pmul(x1, cb1.x)); b4 = fmaxf(b4, p0); b5 = fmaxf(b5, p1);
        upk(p0, p1, pmul(x1, cb1.y)); b6 = fmaxf(b6, p0); b7 = fmaxf(b7, p1);
    }

    float* o = out + (((size_t)b * NCLS) * Hd + h0) * Wd + tx;
    const int cs = Hd * Wd;
    o[0 * cs] = a0; o[1 * cs] = a1; o[2 * cs] = a2; o[3 * cs] = a3;
    o[4 * cs] = a4; o[5 * cs] = a5; o[6 * cs] = a6; o[7 * cs] = a7;
    o += Wd;
    o[0 * cs] = b0; o[1 * cs] = b1; o[2 * cs] = b2; o[3 * cs] = b3;
    o[4 * cs] = b4; o[5 * cs] = b5; o[6 * cs] = b6; o[7 * cs] = b7;
}

extern "C" void kernel_launch(void* const* d_in, const int* in_sizes, int n_in,
                              void* d_out, int out_size)
{
    const float* in = (const float*)d_in[0];
    float* out = (float*)d_out;
    int B = in_sizes[0] / (INCH * NUMB);   // 16

    prep_kernel<<<dim3(2, B), 1024>>>(in);

    cudaLaunchConfig_t cfg = {};
    cfg.gridDim  = dim3(NP / 2, B);        // (32, B) = 512 CTAs
    cfg.blockDim = dim3(Wd, 2);            // 128 x 2 = 256 threads
    cudaLaunchAttribute attr[1];
    attr[0].id = cudaLaunchAttributeProgrammaticStreamSerialization;
    attr[0].val.programmaticStreamSerializationAllowed = 1;
    cfg.attrs = attr;
    cfg.numAttrs = 1;
    cudaLaunchKernelEx(&cfg, layout_bbox_main, out);
}